// round 12
// baseline (speedup 1.0000x reference)
#include <cuda_runtime.h>
#include <cuda_bf16.h>
#include <mma.h>
#include <math.h>
#include <stdint.h>

using namespace nvcuda;

// ---------------------------------------------------------------------------
#define BB 4
#define NN 4096
#define KK 32
#define DP 128
#define DC 69
#define NPTS (BB*NN)
#define ALPHA 0.2f

#define GRID 152
#define NTILES 8192           // attn: 64 ptk-rows per tile
#define NTILES2 8192          // disf: 64 ptk-rows per tile

__device__ float g_pooled[NPTS * DP];

__device__ __forceinline__ void bf16_split(float v, __nv_bfloat16& h,
                                           __nv_bfloat16& l) {
    h = __float2bfloat16_rn(v);
    l = __float2bfloat16_rn(v - __bfloat162float(h));
}
__device__ __forceinline__ uint32_t pack2(__nv_bfloat16 a, __nv_bfloat16 b) {
    return (uint32_t)__bfloat16_as_ushort(a) |
           ((uint32_t)__bfloat16_as_ushort(b) << 16);
}
__device__ __forceinline__ float2 upk_bf2(uint32_t v) {
    __nv_bfloat162 b = *(__nv_bfloat162*)&v;
    return make_float2(__bfloat162float(b.x), __bfloat162float(b.y));
}
__device__ __forceinline__ uint32_t smem_u32(const void* p) {
    uint32_t a;
    asm("{ .reg .u64 t; cvta.to.shared.u64 t, %1; cvt.u32.u64 %0, t; }"
        : "=r"(a) : "l"(p));
    return a;
}
#define NAMED_BAR(id, cnt) \
    asm volatile("bar.sync %0, %1;" :: "r"(id), "r"(cnt) : "memory")

#define CP_ASYNC16(dst, src) \
    asm volatile("cp.async.cg.shared.global [%0], [%1], 16;" \
        :: "r"((uint32_t)(dst)), "l"(src) : "memory")
#define CP_COMMIT() asm volatile("cp.async.commit_group;" ::: "memory")
#define CP_WAIT0()  asm volatile("cp.async.wait_group 0;" ::: "memory")

__device__ __forceinline__ void ldsm4(uint32_t* r, uint32_t addr) {
    asm volatile("ldmatrix.sync.aligned.m8n8.x4.shared.b16 {%0,%1,%2,%3}, [%4];"
        : "=r"(r[0]), "=r"(r[1]), "=r"(r[2]), "=r"(r[3]) : "r"(addr));
}
__device__ __forceinline__ void ldsm4t(uint32_t* r, uint32_t addr) {
    asm volatile("ldmatrix.sync.aligned.m8n8.x4.trans.shared.b16 {%0,%1,%2,%3}, [%4];"
        : "=r"(r[0]), "=r"(r[1]), "=r"(r[2]), "=r"(r[3]) : "r"(addr));
}
__device__ __forceinline__ void mma16816(float* d, const uint32_t* a,
                                         const uint32_t* b) {
    asm volatile("mma.sync.aligned.m16n8k16.row.col.f32.bf16.bf16.f32 "
        "{%0,%1,%2,%3}, {%4,%5,%6,%7}, {%8,%9}, {%0,%1,%2,%3};"
        : "+f"(d[0]), "+f"(d[1]), "+f"(d[2]), "+f"(d[3])
        : "r"(a[0]), "r"(a[1]), "r"(a[2]), "r"(a[3]), "r"(b[0]), "r"(b[1]));
}

// ---------------------------------------------------------------------------
// Fused kernel smem layout (bytes)
// ---------------------------------------------------------------------------
#define A_LDA 136
#define D_LDW 136
#define D_LDG 88
#define FX_AH   0          // [128][136] bf16 = 34816
#define FX_AL   34816
#define FX_NH   69632      // [64][136] bf16 = 17408
#define FX_NL   87040
#define FX_RAW  104448     // attn staging [64][128] fp32 = 32768
#define FX_W2H  137216     // [80][136] bf16 = 21760
#define FX_W2L  158976
#define FX_DGH  180736     // [64][88] bf16 = 11264
#define FX_DGL  192000
#define FX_RAWD 203264     // disf staging: fn 16384 | gn 768 | f 512 = 17664
#define SMEM_FUSED 220928

// ============================================================================
// Fused attn+disf: warps 0-7 = attn, warps 8-15 = disf; both cp.async piped.
// ============================================================================
__global__ void __launch_bounds__(512, 1)
fused_kernel(const float* __restrict__ nfn, const float* __restrict__ a,
             const float* __restrict__ g, const float* __restrict__ f,
             const float* __restrict__ gn, const float* __restrict__ fn,
             const float* __restrict__ w2, const float* __restrict__ b2,
             float* __restrict__ disf) {
    extern __shared__ char sm[];
    __nv_bfloat16* a_h = (__nv_bfloat16*)(sm + FX_AH);
    __nv_bfloat16* a_l = (__nv_bfloat16*)(sm + FX_AL);
    __nv_bfloat16* n_h = (__nv_bfloat16*)(sm + FX_NH);
    __nv_bfloat16* n_l = (__nv_bfloat16*)(sm + FX_NL);
    float* raw = (float*)(sm + FX_RAW);
    __nv_bfloat16* w2h = (__nv_bfloat16*)(sm + FX_W2H);
    __nv_bfloat16* w2l = (__nv_bfloat16*)(sm + FX_W2L);
    __nv_bfloat16* dgh = (__nv_bfloat16*)(sm + FX_DGH);
    __nv_bfloat16* dgl = (__nv_bfloat16*)(sm + FX_DGL);
    float* fn_s = (float*)(sm + FX_RAWD);          // [64][64]
    float* gn_s = fn_s + 4096;                     // [64][3]
    float* f_s = gn_s + 192;                       // [2][64]

    const int tid = threadIdx.x;
    const int bid = blockIdx.x;

    // one-time: split a (attn) and permuted w2+bias (disf)
    for (int idx = tid; idx < 128 * 128; idx += 512) {
        int j = idx >> 7, d = idx & 127;
        __nv_bfloat16 h, l;
        bf16_split(a[idx], h, l);
        a_h[j * A_LDA + d] = h;
        a_l[j * A_LDA + d] = l;
    }
    for (int idx = tid; idx < 80 * 128; idx += 512) {
        int ch = idx >> 7, dd = idx & 127;
        float v = 0.f;
        if (ch < 64) v = w2[(3 + ch) * 128 + dd];
        else if (ch < 67) v = w2[(ch - 64) * 128 + dd];
        else if (ch < 69) v = w2[ch * 128 + dd];
        else if (ch == 69) v = b2[dd];
        __nv_bfloat16 h, l;
        bf16_split(v, h, l);
        w2h[ch * D_LDW + dd] = h;
        w2l[ch * D_LDW + dd] = l;
    }
    __syncthreads();

    if (tid < 256) {
        // ==================== attn pipeline (warps 0-7) ====================
        const int u = tid;
        const int w = u >> 5;
        const int lane = u & 31;
        const int wm = w & 1;
        const int wn = w >> 1;
        const int qrow = lane >> 2;
        const int qc = (lane & 3) << 1;
        const int lrow = lane & 15;
        const int lcol = (lane >> 4) << 3;
        const uint32_t nh_smb = smem_u32(n_h);
        const uint32_t nl_smb = smem_u32(n_l);
        const uint32_t ah_smb = smem_u32(a_h);
        const uint32_t al_smb = smem_u32(a_l);
        const uint32_t raw_smb = smem_u32(raw);

        const int nt = (NTILES - bid + GRID - 1) / GRID;

        // prologue: cp.async tile 0 -> raw
        {
            const char* src = (const char*)(nfn + (size_t)bid * 8192) + u * 16;
            uint32_t dst = raw_smb + u * 16;
#pragma unroll
            for (int q = 0; q < 8; q++) CP_ASYNC16(dst + q * 4096, src + q * 4096);
            CP_COMMIT();
        }

        for (int j = 0; j < nt; j++) {
            const int tile = bid + j * GRID;

            // ---- phase 1: raw ready; split raw -> n_h/n_l ----
            CP_WAIT0();
            NAMED_BAR(1, 256);
#pragma unroll
            for (int q = 0; q < 8; q++) {
                int v = u + 256 * q;
                float4 x = ((const float4*)raw)[v];
                __nv_bfloat16 h0, l0, h1, l1, h2, l2, h3, l3;
                bf16_split(x.x, h0, l0);
                bf16_split(x.y, h1, l1);
                bf16_split(x.z, h2, l2);
                bf16_split(x.w, h3, l3);
                int fidx = v * 4;
                int r = fidx >> 7, c = fidx & 127;
                *(uint2*)(n_h + r * A_LDA + c) =
                    make_uint2(pack2(h0, h1), pack2(h2, h3));
                *(uint2*)(n_l + r * A_LDA + c) =
                    make_uint2(pack2(l0, l1), pack2(l2, l3));
            }
            NAMED_BAR(1, 256);   // split done: n bufs ready, raw free

            if (j + 1 < nt) {
                const char* src =
                    (const char*)(nfn + (size_t)(bid + (size_t)(j + 1) * GRID) * 8192) +
                    u * 16;
                uint32_t dst = raw_smb + u * 16;
#pragma unroll
                for (int q = 0; q < 8; q++)
                    CP_ASYNC16(dst + q * 4096, src + q * 4096);
                CP_COMMIT();
            }

            // ---- phase 2: mma bf16x3, save h A-frags for epilogue ----
            float acc[2][4][4];
#pragma unroll
            for (int mi = 0; mi < 2; mi++)
#pragma unroll
                for (int ni = 0; ni < 4; ni++)
#pragma unroll
                    for (int r = 0; r < 4; r++) acc[mi][ni][r] = 0.f;

            uint32_t nsav[2][2][4];

#pragma unroll
            for (int kk = 0; kk < 8; kk++) {
                uint32_t ah[2][4], al[2][4];
#pragma unroll
                for (int mi = 0; mi < 2; mi++) {
                    const int row = wm * 32 + mi * 16 + lrow;
                    const uint32_t boff =
                        (uint32_t)(row * (A_LDA * 2) + (kk * 16 + lcol) * 2);
                    ldsm4(ah[mi], nh_smb + boff);
                    ldsm4(al[mi], nl_smb + boff);
                }
                if ((kk >> 1) == wn) {
#pragma unroll
                    for (int mi = 0; mi < 2; mi++)
#pragma unroll
                        for (int r = 0; r < 4; r++)
                            nsav[mi][kk & 1][r] = ah[mi][r];
                }
#pragma unroll
                for (int grp = 0; grp < 2; grp++) {
                    uint32_t bh[4], bl[4];
                    const uint32_t boff =
                        (uint32_t)((kk * 16 + lrow) * (A_LDA * 2) +
                                   (wn * 32 + grp * 16 + lcol) * 2);
                    ldsm4t(bh, ah_smb + boff);
                    ldsm4t(bl, al_smb + boff);
#pragma unroll
                    for (int mi = 0; mi < 2; mi++)
#pragma unroll
                        for (int jj = 0; jj < 2; jj++) {
                            float* d = acc[mi][grp * 2 + jj];
                            mma16816(d, ah[mi], bh + 2 * jj);
                            mma16816(d, ah[mi], bl + 2 * jj);
                            mma16816(d, al[mi], bh + 2 * jj);
                        }
                }
            }

            // ---- phase 3: fragment-resident softmax + pooled ----
            {
                float es[8], pl[8];
#pragma unroll
                for (int c = 0; c < 8; c++) { es[c] = 0.f; pl[c] = 0.f; }

#pragma unroll
                for (int mi = 0; mi < 2; mi++)
#pragma unroll
                    for (int hr = 0; hr < 2; hr++) {
                        const int trow = wm * 32 + mi * 16 + qrow + 8 * hr;
#pragma unroll
                        for (int ni = 0; ni < 4; ni++) {
                            const int col = wn * 32 + ni * 8 + qc;
                            float2 hp = upk_bf2(
                                nsav[mi][ni >> 1][hr + 2 * (ni & 1)]);
                            float2 lp = upk_bf2(
                                *(const uint32_t*)(n_l + trow * A_LDA + col));
                            float n0 = hp.x + lp.x, n1 = hp.y + lp.y;
                            float v0 = acc[mi][ni][hr * 2 + 0];
                            float v1 = acc[mi][ni][hr * 2 + 1];
                            v0 = (v0 > 0.f) ? v0 : ALPHA * v0;
                            v1 = (v1 > 0.f) ? v1 : ALPHA * v1;
                            float e0 = __expf(v0), e1 = __expf(v1);
                            es[ni * 2 + 0] += e0;
                            es[ni * 2 + 1] += e1;
                            pl[ni * 2 + 0] += e0 * n0;
                            pl[ni * 2 + 1] += e1 * n1;
                        }
                    }
#pragma unroll
                for (int c = 0; c < 8; c++) {
#pragma unroll
                    for (int m = 4; m <= 16; m <<= 1) {
                        es[c] += __shfl_xor_sync(0xffffffffu, es[c], m);
                        pl[c] += __shfl_xor_sync(0xffffffffu, pl[c], m);
                    }
                }
                if (lane < 4) {
                    float* dst = g_pooled + (size_t)(tile * 2 + wm) * 128 +
                                 wn * 32 + 2 * lane;
#pragma unroll
                    for (int ni = 0; ni < 4; ni++) {
                        float2 v =
                            make_float2(__fdividef(pl[2 * ni], es[2 * ni]),
                                        __fdividef(pl[2 * ni + 1], es[2 * ni + 1]));
                        *(float2*)(dst + ni * 8) = v;
                    }
                }
            }
        }
    } else {
        // ==================== disf pipeline (warps 8-15), cp.async piped ===
        const int u = tid - 256;
        const int w = u >> 5;
        const int wm = w & 1;
        const int wn = w >> 1;
        const int r = u >> 2;          // row 0..63
        const int q = u & 3;           // 16-channel chunk
        const int p = r >> 5;
        const uint32_t rawd_smb = smem_u32(fn_s);

        const int nt = (NTILES2 - bid + GRID - 1) / GRID;

        // prologue: cp.async disf tile 0 (fn | gn | f)
        {
            const int tile = bid;
            const char* fsrc = (const char*)(fn + (size_t)tile * 4096);
            const char* gsrc = (const char*)(gn + (size_t)tile * 192);
            const char* psrc = (const char*)(f + (size_t)tile * 128);
#pragma unroll
            for (int i = 0; i < 4; i++)
                CP_ASYNC16(rawd_smb + (u + 256 * i) * 16, fsrc + (u + 256 * i) * 16);
            if (u < 48) CP_ASYNC16(rawd_smb + 16384 + u * 16, gsrc + u * 16);
            else if (u < 80) {
                int i = u - 48;
                CP_ASYNC16(rawd_smb + 17152 + i * 16, psrc + i * 16);
            }
            CP_COMMIT();
        }

        for (int j = 0; j < nt; j++) {
            const int tile = bid + j * GRID;
            const int grow = tile * 64 + r;

            CP_WAIT0();
            NAMED_BAR(2, 256);   // raw_d visible; dgf free (prev wmma done)

            // ---- build dgf from smem ----
            {
                float pf[16];
                float df2 = 0.f;
                const float4* fv = (const float4*)(fn_s + r * 64 + q * 16);
                const float4* pv = (const float4*)(f_s + p * 64 + q * 16);
#pragma unroll
                for (int i = 0; i < 4; i++) {
                    float4 A = fv[i], F = pv[i];
                    pf[i * 4 + 0] = F.x - A.x;
                    pf[i * 4 + 1] = F.y - A.y;
                    pf[i * 4 + 2] = F.z - A.z;
                    pf[i * 4 + 3] = F.w - A.w;
                    float t0 = F.x - 2.f * A.x, t1 = F.y - 2.f * A.y;
                    float t2 = F.z - 2.f * A.z, t3 = F.w - 2.f * A.w;
                    df2 += t0 * t0 + t1 * t1 + t2 * t2 + t3 * t3;
                }
                uint4* dsth = (uint4*)(dgh + r * D_LDG + q * 16);
                uint4* dstl = (uint4*)(dgl + r * D_LDG + q * 16);
                uint32_t hh[8], ll[8];
#pragma unroll
                for (int i = 0; i < 8; i++) {
                    __nv_bfloat16 h0, l0, h1, l1;
                    bf16_split(pf[2 * i], h0, l0);
                    bf16_split(pf[2 * i + 1], h1, l1);
                    hh[i] = pack2(h0, h1);
                    ll[i] = pack2(l0, l1);
                }
                dsth[0] = make_uint4(hh[0], hh[1], hh[2], hh[3]);
                dsth[1] = make_uint4(hh[4], hh[5], hh[6], hh[7]);
                dstl[0] = make_uint4(ll[0], ll[1], ll[2], ll[3]);
                dstl[1] = make_uint4(ll[4], ll[5], ll[6], ll[7]);

                df2 += __shfl_xor_sync(0xffffffffu, df2, 1);
                df2 += __shfl_xor_sync(0xffffffffu, df2, 2);

                if (q == 0) {
                    float tail[16];
#pragma unroll
                    for (int i = 0; i < 16; i++) tail[i] = 0.f;
                    float dg2 = 0.f;
#pragma unroll
                    for (int c = 0; c < 3; c++) {
                        float gv = g[(size_t)(tile * 2 + p) * 3 + c];
                        float gnv = gn_s[r * 3 + c];
                        tail[c] = gv - gnv;
                        float t = gv - 2.f * gnv;
                        dg2 += t * t;
                    }
                    tail[3] = sqrtf(dg2);
                    tail[4] = sqrtf(df2);
                    tail[5] = 1.0f;
                    uint32_t th[8], tl[8];
#pragma unroll
                    for (int i = 0; i < 8; i++) {
                        __nv_bfloat16 h0, l0, h1, l1;
                        bf16_split(tail[2 * i], h0, l0);
                        bf16_split(tail[2 * i + 1], h1, l1);
                        th[i] = pack2(h0, h1);
                        tl[i] = pack2(l0, l1);
                    }
                    uint4* dh = (uint4*)(dgh + r * D_LDG + 64);
                    uint4* dl = (uint4*)(dgl + r * D_LDG + 64);
                    dh[0] = make_uint4(th[0], th[1], th[2], th[3]);
                    dh[1] = make_uint4(th[4], th[5], th[6], th[7]);
                    dl[0] = make_uint4(tl[0], tl[1], tl[2], tl[3]);
                    dl[1] = make_uint4(tl[4], tl[5], tl[6], tl[7]);
                }
            }
            NAMED_BAR(2, 256);   // dgf ready, raw_d free

            // issue next disf tile's cp.async; overlaps wmma below
            if (j + 1 < nt) {
                const int ntile = bid + (j + 1) * GRID;
                const char* fsrc = (const char*)(fn + (size_t)ntile * 4096);
                const char* gsrc = (const char*)(gn + (size_t)ntile * 192);
                const char* psrc = (const char*)(f + (size_t)ntile * 128);
#pragma unroll
                for (int i = 0; i < 4; i++)
                    CP_ASYNC16(rawd_smb + (u + 256 * i) * 16,
                               fsrc + (u + 256 * i) * 16);
                if (u < 48) CP_ASYNC16(rawd_smb + 16384 + u * 16, gsrc + u * 16);
                else if (u < 80) {
                    int i = u - 48;
                    CP_ASYNC16(rawd_smb + 17152 + i * 16, psrc + i * 16);
                }
                CP_COMMIT();
            }

            // ---- wmma bf16x3 (K=80), 32x32 warp tiles, store to gmem ----
            {
                wmma::fragment<wmma::accumulator, 16, 16, 16, float> acc[2][2];
#pragma unroll
                for (int mi = 0; mi < 2; mi++)
#pragma unroll
                    for (int ni = 0; ni < 2; ni++)
                        wmma::fill_fragment(acc[mi][ni], 0.0f);
#pragma unroll
                for (int kk = 0; kk < 5; kk++) {
                    wmma::fragment<wmma::matrix_a, 16, 16, 16, __nv_bfloat16,
                                   wmma::row_major> dh[2], dl[2];
#pragma unroll
                    for (int mi = 0; mi < 2; mi++) {
                        const int row = wm * 32 + mi * 16;
                        wmma::load_matrix_sync(dh[mi],
                            dgh + row * D_LDG + kk * 16, D_LDG);
                        wmma::load_matrix_sync(dl[mi],
                            dgl + row * D_LDG + kk * 16, D_LDG);
                    }
#pragma unroll
                    for (int ni = 0; ni < 2; ni++) {
                        wmma::fragment<wmma::matrix_b, 16, 16, 16, __nv_bfloat16,
                                       wmma::row_major> wh, wl;
                        const int col = wn * 32 + ni * 16;
                        wmma::load_matrix_sync(wh,
                            w2h + kk * 16 * D_LDW + col, D_LDW);
                        wmma::load_matrix_sync(wl,
                            w2l + kk * 16 * D_LDW + col, D_LDW);
#pragma unroll
                        for (int mi = 0; mi < 2; mi++) {
                            wmma::mma_sync(acc[mi][ni], dh[mi], wh, acc[mi][ni]);
                            wmma::mma_sync(acc[mi][ni], dh[mi], wl, acc[mi][ni]);
                            wmma::mma_sync(acc[mi][ni], dl[mi], wh, acc[mi][ni]);
                        }
                    }
                }
                float* dst = disf + (size_t)tile * 64 * 128;
#pragma unroll
                for (int mi = 0; mi < 2; mi++)
#pragma unroll
                    for (int ni = 0; ni < 2; ni++)
                        wmma::store_matrix_sync(
                            dst + (wm * 32 + mi * 16) * 128 + wn * 32 + ni * 16,
                            acc[mi][ni], 128, wmma::mem_row_major);
            }
            // loop-top bar orders wmma(j) before build(j+1)
        }
    }
}

// ============================================================================
// out = pooled @ w1 + b1 via wmma bf16x3 (unchanged).
// ============================================================================
#define O_LDW 136
#define O_LDE 132
#define OT_WH 0
#define OT_WL 34816
#define OT_B1 69632
#define OT_PH 70144
#define OT_PL 87552
#define OT_ES 104960
#define SMEM_OUT 138752

__global__ void __launch_bounds__(256, 1)
out_wmma_kernel(const float* __restrict__ w1, const float* __restrict__ b1,
                float* __restrict__ out) {
    extern __shared__ char sm[];
    __nv_bfloat16* w1h = (__nv_bfloat16*)(sm + OT_WH);
    __nv_bfloat16* w1l = (__nv_bfloat16*)(sm + OT_WL);
    float* b1s = (float*)(sm + OT_B1);
    __nv_bfloat16* p_h = (__nv_bfloat16*)(sm + OT_PH);
    __nv_bfloat16* p_l = (__nv_bfloat16*)(sm + OT_PL);
    float* e_s = (float*)(sm + OT_ES);

    const int tid = threadIdx.x;
    const int w = tid >> 5;
    const int wm = w & 1;
    const int wn = w >> 1;

    for (int idx = tid; idx < 128 * 128; idx += 256) {
        int j = idx >> 7, d = idx & 127;
        __nv_bfloat16 h, l;
        bf16_split(w1[idx], h, l);
        w1h[j * O_LDW + d] = h;
        w1l[j * O_LDW + d] = l;
    }
    if (tid < 128) b1s[tid] = b1[tid];
    __syncthreads();

    for (int tile = blockIdx.x; tile < NPTS / 64; tile += GRID) {
        const float4* gsrc = (const float4*)(g_pooled + (size_t)tile * 8192);
#pragma unroll
        for (int q = 0; q < 8; q++) {
            int v = tid + 256 * q;
            float4 x = gsrc[v];
            __nv_bfloat16 h0, l0, h1, l1, h2, l2, h3, l3;
            bf16_split(x.x, h0, l0);
            bf16_split(x.y, h1, l1);
            bf16_split(x.z, h2, l2);
            bf16_split(x.w, h3, l3);
            int fidx = v * 4;
            int r = fidx >> 7, c = fidx & 127;
            *(uint2*)(p_h + r * O_LDW + c) = make_uint2(pack2(h0, h1), pack2(h2, h3));
            *(uint2*)(p_l + r * O_LDW + c) = make_uint2(pack2(l0, l1), pack2(l2, l3));
        }
        __syncthreads();

        {
            wmma::fragment<wmma::accumulator, 16, 16, 16, float> acc[2][2];
#pragma unroll
            for (int mi = 0; mi < 2; mi++)
#pragma unroll
                for (int ni = 0; ni < 2; ni++)
                    wmma::fill_fragment(acc[mi][ni], 0.0f);
#pragma unroll
            for (int kk = 0; kk < 8; kk++) {
                wmma::fragment<wmma::matrix_a, 16, 16, 16, __nv_bfloat16,
                               wmma::row_major> ph[2], pl[2];
                wmma::fragment<wmma::matrix_b, 16, 16, 16, __nv_bfloat16,
                               wmma::row_major> wh[2], wl[2];
#pragma unroll
                for (int mi = 0; mi < 2; mi++) {
                    const int row = wm * 32 + mi * 16;
                    wmma::load_matrix_sync(ph[mi], p_h + row * O_LDW + kk * 16, O_LDW);
                    wmma::load_matrix_sync(pl[mi], p_l + row * O_LDW + kk * 16, O_LDW);
                }
#pragma unroll
                for (int ni = 0; ni < 2; ni++) {
                    const int col = wn * 32 + ni * 16;
                    wmma::load_matrix_sync(wh[ni], w1h + kk * 16 * O_LDW + col, O_LDW);
                    wmma::load_matrix_sync(wl[ni], w1l + kk * 16 * O_LDW + col, O_LDW);
                }
#pragma unroll
                for (int mi = 0; mi < 2; mi++)
#pragma unroll
                    for (int ni = 0; ni < 2; ni++) {
                        wmma::mma_sync(acc[mi][ni], ph[mi], wh[ni], acc[mi][ni]);
                        wmma::mma_sync(acc[mi][ni], ph[mi], wl[ni], acc[mi][ni]);
                        wmma::mma_sync(acc[mi][ni], pl[mi], wh[ni], acc[mi][ni]);
                    }
            }
#pragma unroll
            for (int mi = 0; mi < 2; mi++)
#pragma unroll
                for (int ni = 0; ni < 2; ni++)
                    wmma::store_matrix_sync(
                        e_s + (wm * 32 + mi * 16) * O_LDE + wn * 32 + ni * 16,
                        acc[mi][ni], O_LDE, wmma::mem_row_major);
        }
        __syncthreads();

        {
            float* dst = out + (size_t)tile * 8192;
#pragma unroll
            for (int i = 0; i < 8; i++) {
                int v = tid + 256 * i;
                int rr = v >> 5, c4 = v & 31;
                float4 e4 = *(const float4*)(e_s + rr * O_LDE + c4 * 4);
                float4 b4 = *(const float4*)(b1s + c4 * 4);
                e4.x += b4.x; e4.y += b4.y; e4.z += b4.z; e4.w += b4.w;
                ((float4*)dst)[v] = e4;
            }
        }
        __syncthreads();
    }
}

// ============================================================================
// launch
// ============================================================================
extern "C" void kernel_launch(void* const* d_in, const int* in_sizes, int n_in,
                              void* d_out, int out_size) {
    const float* g = (const float*)d_in[0];
    const float* f = (const float*)d_in[1];
    const float* gn = (const float*)d_in[2];
    const float* fn = (const float*)d_in[3];
    const float* nfn = (const float*)d_in[4];
    const float* a = (const float*)d_in[5];
    const float* w2 = (const float*)d_in[6];
    const float* b2 = (const float*)d_in[7];
    const float* w1 = (const float*)d_in[8];
    const float* b1 = (const float*)d_in[9];

    float* out = (float*)d_out;
    float* disf = out + (size_t)NPTS * DP;

    cudaFuncSetAttribute(fused_kernel,
                         cudaFuncAttributeMaxDynamicSharedMemorySize, SMEM_FUSED);
    cudaFuncSetAttribute(out_wmma_kernel,
                         cudaFuncAttributeMaxDynamicSharedMemorySize, SMEM_OUT);

    fused_kernel<<<GRID, 512, SMEM_FUSED>>>(nfn, a, g, f, gn, fn, w2, b2, disf);
    out_wmma_kernel<<<GRID, 256, SMEM_OUT>>>(w1, b1, out);
}

// round 13
// speedup vs baseline: 1.0431x; 1.0431x over previous
#include <cuda_runtime.h>
#include <cuda_bf16.h>
#include <mma.h>
#include <math.h>
#include <stdint.h>

using namespace nvcuda;

// ---------------------------------------------------------------------------
#define BB 4
#define NN 4096
#define KK 32
#define DP 128
#define DC 69
#define NPTS (BB*NN)
#define ALPHA 0.2f

#define GRID 152
#define NTILES 8192           // attn: 64 ptk-rows per tile
#define NTILES2 8192          // disf: 64 ptk-rows per tile

__device__ float g_pooled[NPTS * DP];

__device__ __forceinline__ void bf16_split(float v, __nv_bfloat16& h,
                                           __nv_bfloat16& l) {
    h = __float2bfloat16_rn(v);
    l = __float2bfloat16_rn(v - __bfloat162float(h));
}
__device__ __forceinline__ uint32_t pack2(__nv_bfloat16 a, __nv_bfloat16 b) {
    return (uint32_t)__bfloat16_as_ushort(a) |
           ((uint32_t)__bfloat16_as_ushort(b) << 16);
}
__device__ __forceinline__ float2 upk_bf2(uint32_t v) {
    __nv_bfloat162 b = *(__nv_bfloat162*)&v;
    return make_float2(__bfloat162float(b.x), __bfloat162float(b.y));
}
__device__ __forceinline__ uint32_t smem_u32(const void* p) {
    uint32_t a;
    asm("{ .reg .u64 t; cvta.to.shared.u64 t, %1; cvt.u32.u64 %0, t; }"
        : "=r"(a) : "l"(p));
    return a;
}
#define NAMED_BAR(id, cnt) \
    asm volatile("bar.sync %0, %1;" :: "r"(id), "r"(cnt) : "memory")

#define CP_ASYNC16(dst, src) \
    asm volatile("cp.async.cg.shared.global [%0], [%1], 16;" \
        :: "r"((uint32_t)(dst)), "l"(src) : "memory")
#define CP_COMMIT() asm volatile("cp.async.commit_group;" ::: "memory")
#define CP_WAIT0()  asm volatile("cp.async.wait_group 0;" ::: "memory")

__device__ __forceinline__ void ldsm4(uint32_t* r, uint32_t addr) {
    asm volatile("ldmatrix.sync.aligned.m8n8.x4.shared.b16 {%0,%1,%2,%3}, [%4];"
        : "=r"(r[0]), "=r"(r[1]), "=r"(r[2]), "=r"(r[3]) : "r"(addr));
}
__device__ __forceinline__ void ldsm4t(uint32_t* r, uint32_t addr) {
    asm volatile("ldmatrix.sync.aligned.m8n8.x4.trans.shared.b16 {%0,%1,%2,%3}, [%4];"
        : "=r"(r[0]), "=r"(r[1]), "=r"(r[2]), "=r"(r[3]) : "r"(addr));
}
__device__ __forceinline__ void mma16816(float* d, const uint32_t* a,
                                         const uint32_t* b) {
    asm volatile("mma.sync.aligned.m16n8k16.row.col.f32.bf16.bf16.f32 "
        "{%0,%1,%2,%3}, {%4,%5,%6,%7}, {%8,%9}, {%0,%1,%2,%3};"
        : "+f"(d[0]), "+f"(d[1]), "+f"(d[2]), "+f"(d[3])
        : "r"(a[0]), "r"(a[1]), "r"(a[2]), "r"(a[3]), "r"(b[0]), "r"(b[1]));
}

// ---------------------------------------------------------------------------
// Fused kernel smem layout (bytes) — R11 layout
// ---------------------------------------------------------------------------
#define A_LDA 136
#define D_LDW 136
#define D_LDG 88
#define FX_AH   0          // [128][136] bf16 = 34816
#define FX_AL   34816
#define FX_NH   69632      // [64][136] bf16 = 17408
#define FX_NL   87040
#define FX_RAW  104448     // attn staging [64][128] fp32 = 32768
#define FX_W2H  137216     // [80][136] bf16 = 21760
#define FX_W2L  158976
#define FX_DGH  180736     // [64][88] bf16 = 11264
#define FX_DGL  192000
#define SMEM_FUSED 203264

// ============================================================================
// Fused attn+disf: warps 0-7 = attn (cp.async pipelined), 8-15 = disf (R11).
// ============================================================================
__global__ void __launch_bounds__(512, 1)
fused_kernel(const float* __restrict__ nfn, const float* __restrict__ a,
             const float* __restrict__ g, const float* __restrict__ f,
             const float* __restrict__ gn, const float* __restrict__ fn,
             const float* __restrict__ w2, const float* __restrict__ b2,
             float* __restrict__ disf) {
    extern __shared__ char sm[];
    __nv_bfloat16* a_h = (__nv_bfloat16*)(sm + FX_AH);
    __nv_bfloat16* a_l = (__nv_bfloat16*)(sm + FX_AL);
    __nv_bfloat16* n_h = (__nv_bfloat16*)(sm + FX_NH);
    __nv_bfloat16* n_l = (__nv_bfloat16*)(sm + FX_NL);
    float* raw = (float*)(sm + FX_RAW);
    __nv_bfloat16* w2h = (__nv_bfloat16*)(sm + FX_W2H);
    __nv_bfloat16* w2l = (__nv_bfloat16*)(sm + FX_W2L);
    __nv_bfloat16* dgh = (__nv_bfloat16*)(sm + FX_DGH);
    __nv_bfloat16* dgl = (__nv_bfloat16*)(sm + FX_DGL);

    const int tid = threadIdx.x;
    const int bid = blockIdx.x;

    // one-time: split a (attn) and permuted w2+bias (disf)
    for (int idx = tid; idx < 128 * 128; idx += 512) {
        int j = idx >> 7, d = idx & 127;
        __nv_bfloat16 h, l;
        bf16_split(a[idx], h, l);
        a_h[j * A_LDA + d] = h;
        a_l[j * A_LDA + d] = l;
    }
    for (int idx = tid; idx < 80 * 128; idx += 512) {
        int ch = idx >> 7, dd = idx & 127;
        float v = 0.f;
        if (ch < 64) v = w2[(3 + ch) * 128 + dd];
        else if (ch < 67) v = w2[(ch - 64) * 128 + dd];
        else if (ch < 69) v = w2[ch * 128 + dd];
        else if (ch == 69) v = b2[dd];
        __nv_bfloat16 h, l;
        bf16_split(v, h, l);
        w2h[ch * D_LDW + dd] = h;
        w2l[ch * D_LDW + dd] = l;
    }
    __syncthreads();

    if (tid < 256) {
        // ==================== attn pipeline (warps 0-7) ====================
        const int u = tid;
        const int w = u >> 5;
        const int lane = u & 31;
        const int wm = w & 1;
        const int wn = w >> 1;
        const int qrow = lane >> 2;
        const int qc = (lane & 3) << 1;
        const int lrow = lane & 15;
        const int lcol = (lane >> 4) << 3;
        const uint32_t nh_smb = smem_u32(n_h);
        const uint32_t nl_smb = smem_u32(n_l);
        const uint32_t ah_smb = smem_u32(a_h);
        const uint32_t al_smb = smem_u32(a_l);
        const uint32_t raw_smb = smem_u32(raw);

        const int nt = (NTILES - bid + GRID - 1) / GRID;

        // prologue: cp.async tile 0 -> raw
        {
            const char* src = (const char*)(nfn + (size_t)bid * 8192) + u * 16;
            uint32_t dst = raw_smb + u * 16;
#pragma unroll
            for (int q = 0; q < 8; q++) CP_ASYNC16(dst + q * 4096, src + q * 4096);
            CP_COMMIT();
        }

        for (int j = 0; j < nt; j++) {
            const int tile = bid + j * GRID;

            // ---- phase 1: raw ready; split raw -> n_h/n_l ----
            CP_WAIT0();
            NAMED_BAR(1, 256);
#pragma unroll
            for (int q = 0; q < 8; q++) {
                int v = u + 256 * q;
                float4 x = ((const float4*)raw)[v];
                __nv_bfloat16 h0, l0, h1, l1, h2, l2, h3, l3;
                bf16_split(x.x, h0, l0);
                bf16_split(x.y, h1, l1);
                bf16_split(x.z, h2, l2);
                bf16_split(x.w, h3, l3);
                int fidx = v * 4;
                int r = fidx >> 7, c = fidx & 127;
                *(uint2*)(n_h + r * A_LDA + c) =
                    make_uint2(pack2(h0, h1), pack2(h2, h3));
                *(uint2*)(n_l + r * A_LDA + c) =
                    make_uint2(pack2(l0, l1), pack2(l2, l3));
            }
            NAMED_BAR(1, 256);   // split done: n bufs ready, raw free

            if (j + 1 < nt) {
                const char* src =
                    (const char*)(nfn + (size_t)(bid + (size_t)(j + 1) * GRID) * 8192) +
                    u * 16;
                uint32_t dst = raw_smb + u * 16;
#pragma unroll
                for (int q = 0; q < 8; q++)
                    CP_ASYNC16(dst + q * 4096, src + q * 4096);
                CP_COMMIT();
            }

            // ---- phase 2: mma bf16x3, save h A-frags for epilogue ----
            float acc[2][4][4];
#pragma unroll
            for (int mi = 0; mi < 2; mi++)
#pragma unroll
                for (int ni = 0; ni < 4; ni++)
#pragma unroll
                    for (int r = 0; r < 4; r++) acc[mi][ni][r] = 0.f;

            uint32_t nsav[2][2][4];

#pragma unroll
            for (int kk = 0; kk < 8; kk++) {
                uint32_t ah[2][4], al[2][4];
#pragma unroll
                for (int mi = 0; mi < 2; mi++) {
                    const int row = wm * 32 + mi * 16 + lrow;
                    const uint32_t boff =
                        (uint32_t)(row * (A_LDA * 2) + (kk * 16 + lcol) * 2);
                    ldsm4(ah[mi], nh_smb + boff);
                    ldsm4(al[mi], nl_smb + boff);
                }
                if ((kk >> 1) == wn) {
#pragma unroll
                    for (int mi = 0; mi < 2; mi++)
#pragma unroll
                        for (int r = 0; r < 4; r++)
                            nsav[mi][kk & 1][r] = ah[mi][r];
                }
#pragma unroll
                for (int grp = 0; grp < 2; grp++) {
                    uint32_t bh[4], bl[4];
                    const uint32_t boff =
                        (uint32_t)((kk * 16 + lrow) * (A_LDA * 2) +
                                   (wn * 32 + grp * 16 + lcol) * 2);
                    ldsm4t(bh, ah_smb + boff);
                    ldsm4t(bl, al_smb + boff);
#pragma unroll
                    for (int mi = 0; mi < 2; mi++)
#pragma unroll
                        for (int jj = 0; jj < 2; jj++) {
                            float* d = acc[mi][grp * 2 + jj];
                            mma16816(d, ah[mi], bh + 2 * jj);
                            mma16816(d, ah[mi], bl + 2 * jj);
                            mma16816(d, al[mi], bh + 2 * jj);
                        }
                }
            }

            // ---- phase 3: fragment-resident softmax + pooled ----
            {
                float es[8], pl[8];
#pragma unroll
                for (int c = 0; c < 8; c++) { es[c] = 0.f; pl[c] = 0.f; }

#pragma unroll
                for (int mi = 0; mi < 2; mi++)
#pragma unroll
                    for (int hr = 0; hr < 2; hr++) {
                        const int trow = wm * 32 + mi * 16 + qrow + 8 * hr;
#pragma unroll
                        for (int ni = 0; ni < 4; ni++) {
                            const int col = wn * 32 + ni * 8 + qc;
                            float2 hp = upk_bf2(
                                nsav[mi][ni >> 1][hr + 2 * (ni & 1)]);
                            float2 lp = upk_bf2(
                                *(const uint32_t*)(n_l + trow * A_LDA + col));
                            float n0 = hp.x + lp.x, n1 = hp.y + lp.y;
                            float v0 = acc[mi][ni][hr * 2 + 0];
                            float v1 = acc[mi][ni][hr * 2 + 1];
                            v0 = (v0 > 0.f) ? v0 : ALPHA * v0;
                            v1 = (v1 > 0.f) ? v1 : ALPHA * v1;
                            float e0 = __expf(v0), e1 = __expf(v1);
                            es[ni * 2 + 0] += e0;
                            es[ni * 2 + 1] += e1;
                            pl[ni * 2 + 0] += e0 * n0;
                            pl[ni * 2 + 1] += e1 * n1;
                        }
                    }
#pragma unroll
                for (int c = 0; c < 8; c++) {
#pragma unroll
                    for (int m = 4; m <= 16; m <<= 1) {
                        es[c] += __shfl_xor_sync(0xffffffffu, es[c], m);
                        pl[c] += __shfl_xor_sync(0xffffffffu, pl[c], m);
                    }
                }
                if (lane < 4) {
                    float* dst = g_pooled + (size_t)(tile * 2 + wm) * 128 +
                                 wn * 32 + 2 * lane;
#pragma unroll
                    for (int ni = 0; ni < 4; ni++) {
                        float2 v =
                            make_float2(__fdividef(pl[2 * ni], es[2 * ni]),
                                        __fdividef(pl[2 * ni + 1], es[2 * ni + 1]));
                        *(float2*)(dst + ni * 8) = v;
                    }
                }
            }
        }
    } else {
        // ==================== disf pipeline (warps 8-15) — R11 version =====
        const int u = tid - 256;
        const int w = u >> 5;
        const int wm = w & 1;          // 32-row block
        const int wn = w >> 1;         // 32-col block
        const int r = u >> 2;          // row 0..63
        const int q = u & 3;           // 16-channel chunk
        const int p = r >> 5;

        const int nt = (NTILES2 - bid + GRID - 1) / GRID;
        for (int j = 0; j < nt; j++) {
            const int tile = bid + j * GRID;
            const int grow = tile * 64 + r;

            // ---- build dgf straight from LDG ----
            {
                const float4* fnp =
                    (const float4*)(fn + (size_t)grow * 64 + q * 16);
                const float4* fp =
                    (const float4*)(f + (size_t)(tile * 2 + p) * 64 + q * 16);
                float pf[16];
                float df2 = 0.f;
#pragma unroll
                for (int i = 0; i < 4; i++) {
                    float4 A = fnp[i], F = fp[i];
                    pf[i * 4 + 0] = F.x - A.x;
                    pf[i * 4 + 1] = F.y - A.y;
                    pf[i * 4 + 2] = F.z - A.z;
                    pf[i * 4 + 3] = F.w - A.w;
                    float t0 = F.x - 2.f * A.x, t1 = F.y - 2.f * A.y;
                    float t2 = F.z - 2.f * A.z, t3 = F.w - 2.f * A.w;
                    df2 += t0 * t0 + t1 * t1 + t2 * t2 + t3 * t3;
                }
                uint4* dsth = (uint4*)(dgh + r * D_LDG + q * 16);
                uint4* dstl = (uint4*)(dgl + r * D_LDG + q * 16);
                uint32_t hh[8], ll[8];
#pragma unroll
                for (int i = 0; i < 8; i++) {
                    __nv_bfloat16 h0, l0, h1, l1;
                    bf16_split(pf[2 * i], h0, l0);
                    bf16_split(pf[2 * i + 1], h1, l1);
                    hh[i] = pack2(h0, h1);
                    ll[i] = pack2(l0, l1);
                }
                dsth[0] = make_uint4(hh[0], hh[1], hh[2], hh[3]);
                dsth[1] = make_uint4(hh[4], hh[5], hh[6], hh[7]);
                dstl[0] = make_uint4(ll[0], ll[1], ll[2], ll[3]);
                dstl[1] = make_uint4(ll[4], ll[5], ll[6], ll[7]);

                df2 += __shfl_xor_sync(0xffffffffu, df2, 1);
                df2 += __shfl_xor_sync(0xffffffffu, df2, 2);

                if (q == 0) {
                    float tail[16];
#pragma unroll
                    for (int i = 0; i < 16; i++) tail[i] = 0.f;
                    float dg2 = 0.f;
#pragma unroll
                    for (int c = 0; c < 3; c++) {
                        float gv = g[(size_t)(tile * 2 + p) * 3 + c];
                        float gnv = gn[(size_t)grow * 3 + c];
                        tail[c] = gv - gnv;
                        float t = gv - 2.f * gnv;
                        dg2 += t * t;
                    }
                    tail[3] = sqrtf(dg2);
                    tail[4] = sqrtf(df2);
                    tail[5] = 1.0f;
                    uint32_t th[8], tl[8];
#pragma unroll
                    for (int i = 0; i < 8; i++) {
                        __nv_bfloat16 h0, l0, h1, l1;
                        bf16_split(tail[2 * i], h0, l0);
                        bf16_split(tail[2 * i + 1], h1, l1);
                        th[i] = pack2(h0, h1);
                        tl[i] = pack2(l0, l1);
                    }
                    uint4* dh = (uint4*)(dgh + r * D_LDG + 64);
                    uint4* dl = (uint4*)(dgl + r * D_LDG + 64);
                    dh[0] = make_uint4(th[0], th[1], th[2], th[3]);
                    dh[1] = make_uint4(th[4], th[5], th[6], th[7]);
                    dl[0] = make_uint4(tl[0], tl[1], tl[2], tl[3]);
                    dl[1] = make_uint4(tl[4], tl[5], tl[6], tl[7]);
                }
            }
            NAMED_BAR(2, 256);

            // ---- wmma bf16x3 (K=80), 32x32 warp tiles, store to gmem ----
            {
                wmma::fragment<wmma::accumulator, 16, 16, 16, float> acc[2][2];
#pragma unroll
                for (int mi = 0; mi < 2; mi++)
#pragma unroll
                    for (int ni = 0; ni < 2; ni++)
                        wmma::fill_fragment(acc[mi][ni], 0.0f);
#pragma unroll
                for (int kk = 0; kk < 5; kk++) {
                    wmma::fragment<wmma::matrix_a, 16, 16, 16, __nv_bfloat16,
                                   wmma::row_major> dh[2], dl[2];
#pragma unroll
                    for (int mi = 0; mi < 2; mi++) {
                        const int row = wm * 32 + mi * 16;
                        wmma::load_matrix_sync(dh[mi],
                            dgh + row * D_LDG + kk * 16, D_LDG);
                        wmma::load_matrix_sync(dl[mi],
                            dgl + row * D_LDG + kk * 16, D_LDG);
                    }
#pragma unroll
                    for (int ni = 0; ni < 2; ni++) {
                        wmma::fragment<wmma::matrix_b, 16, 16, 16, __nv_bfloat16,
                                       wmma::row_major> wh, wl;
                        const int col = wn * 32 + ni * 16;
                        wmma::load_matrix_sync(wh,
                            w2h + kk * 16 * D_LDW + col, D_LDW);
                        wmma::load_matrix_sync(wl,
                            w2l + kk * 16 * D_LDW + col, D_LDW);
#pragma unroll
                        for (int mi = 0; mi < 2; mi++) {
                            wmma::mma_sync(acc[mi][ni], dh[mi], wh, acc[mi][ni]);
                            wmma::mma_sync(acc[mi][ni], dh[mi], wl, acc[mi][ni]);
                            wmma::mma_sync(acc[mi][ni], dl[mi], wh, acc[mi][ni]);
                        }
                    }
                }
                float* dst = disf + (size_t)tile * 64 * 128;
#pragma unroll
                for (int mi = 0; mi < 2; mi++)
#pragma unroll
                    for (int ni = 0; ni < 2; ni++)
                        wmma::store_matrix_sync(
                            dst + (wm * 32 + mi * 16) * 128 + wn * 32 + ni * 16,
                            acc[mi][ni], 128, wmma::mem_row_major);
            }
            NAMED_BAR(2, 256);
        }
    }
}

// ============================================================================
// out = pooled @ w1 + b1: 512 threads = 2 halves, 1 tile each; hand mma,
// bias in-register, direct STG from fragments (no e_s, no extra barriers).
// ============================================================================
#define O_LDW 136
#define GRID_OUT 128
#define OT_WH 0
#define OT_WL 34816
#define OT_B1 69632
#define OT_HB 70144        // per-half: p_h [64][136] + p_l
#define OT_HSZ 34816
#define SMEM_OUT 139776

__global__ void __launch_bounds__(512, 1)
out_mma_kernel(const float* __restrict__ w1, const float* __restrict__ b1,
               float* __restrict__ out) {
    extern __shared__ char sm[];
    __nv_bfloat16* w1h = (__nv_bfloat16*)(sm + OT_WH);   // [128][136]
    __nv_bfloat16* w1l = (__nv_bfloat16*)(sm + OT_WL);
    float* b1s = (float*)(sm + OT_B1);

    const int tid = threadIdx.x;
    const int half = tid >> 8;
    const int u = tid & 255;

    for (int idx = tid; idx < 128 * 128; idx += 512) {
        int j = idx >> 7, d = idx & 127;
        __nv_bfloat16 h, l;
        bf16_split(w1[idx], h, l);
        w1h[j * O_LDW + d] = h;
        w1l[j * O_LDW + d] = l;
    }
    if (tid < 128) b1s[tid] = b1[tid];
    __syncthreads();

    char* hb = sm + OT_HB + half * OT_HSZ;
    __nv_bfloat16* p_h = (__nv_bfloat16*)hb;             // [64][136]
    __nv_bfloat16* p_l = (__nv_bfloat16*)(hb + 17408);

    const int tile = blockIdx.x * 2 + half;              // 256 tiles total

    // stage pooled tile, split hi/lo
    {
        const float4* gsrc = (const float4*)(g_pooled + (size_t)tile * 8192);
#pragma unroll
        for (int q = 0; q < 8; q++) {
            int v = u + 256 * q;
            float4 x = gsrc[v];
            __nv_bfloat16 h0, l0, h1, l1, h2, l2, h3, l3;
            bf16_split(x.x, h0, l0);
            bf16_split(x.y, h1, l1);
            bf16_split(x.z, h2, l2);
            bf16_split(x.w, h3, l3);
            int fidx = v * 4;
            int r = fidx >> 7, c = fidx & 127;
            *(uint2*)(p_h + r * O_LDW + c) = make_uint2(pack2(h0, h1), pack2(h2, h3));
            *(uint2*)(p_l + r * O_LDW + c) = make_uint2(pack2(l0, l1), pack2(l2, l3));
        }
    }
    NAMED_BAR(1 + half, 256);

    // mma: warp tile 16 rows x 64 cols; 8 warps = 4 wm x 2 wn
    const int w = u >> 5;
    const int lane = u & 31;
    const int wm = w & 3;
    const int wn = w >> 2;
    const int qrow = lane >> 2;
    const int qc = (lane & 3) << 1;
    const int lrow = lane & 15;
    const int lcol = (lane >> 4) << 3;
    const uint32_t ph_smb = smem_u32(p_h);
    const uint32_t pl_smb = smem_u32(p_l);
    const uint32_t wh_smb = smem_u32(w1h);
    const uint32_t wl_smb = smem_u32(w1l);

    // preload bias pairs for the 8 n8-fragments this thread touches
    float2 b1v[8];
#pragma unroll
    for (int grp = 0; grp < 4; grp++)
#pragma unroll
        for (int jj = 0; jj < 2; jj++) {
            int col = wn * 64 + grp * 16 + jj * 8 + qc;
            b1v[grp * 2 + jj] = *(const float2*)(b1s + col);
        }

    float acc[8][4];
#pragma unroll
    for (int c = 0; c < 8; c++)
#pragma unroll
        for (int r = 0; r < 4; r++) acc[c][r] = 0.f;

#pragma unroll
    for (int kk = 0; kk < 8; kk++) {
        uint32_t ph[4], pl[4];
        {
            const int row = wm * 16 + lrow;
            const uint32_t boff =
                (uint32_t)(row * (O_LDW * 2) + (kk * 16 + lcol) * 2);
            ldsm4(ph, ph_smb + boff);
            ldsm4(pl, pl_smb + boff);
        }
#pragma unroll
        for (int grp = 0; grp < 4; grp++) {
            uint32_t bh[4], bl[4];
            const uint32_t boff =
                (uint32_t)((kk * 16 + lrow) * (O_LDW * 2) +
                           (wn * 64 + grp * 16 + lcol) * 2);
            ldsm4t(bh, wh_smb + boff);
            ldsm4t(bl, wl_smb + boff);
#pragma unroll
            for (int jj = 0; jj < 2; jj++) {
                float* d = acc[grp * 2 + jj];
                mma16816(d, ph, bh + 2 * jj);
                mma16816(d, ph, bl + 2 * jj);
                mma16816(d, pl, bh + 2 * jj);
            }
        }
    }

    // direct STG from fragments, bias added in-register
    {
        float* base = out + (size_t)tile * 8192;
#pragma unroll
        for (int grp = 0; grp < 4; grp++)
#pragma unroll
            for (int jj = 0; jj < 2; jj++) {
                const int c8 = grp * 2 + jj;
                const int col = wn * 64 + grp * 16 + jj * 8 + qc;
#pragma unroll
                for (int hr = 0; hr < 2; hr++) {
                    const int row = wm * 16 + qrow + 8 * hr;
                    float2 v = make_float2(acc[c8][hr * 2 + 0] + b1v[c8].x,
                                           acc[c8][hr * 2 + 1] + b1v[c8].y);
                    *(float2*)(base + row * 128 + col) = v;
                }
            }
    }
}

// ============================================================================
// launch
// ============================================================================
extern "C" void kernel_launch(void* const* d_in, const int* in_sizes, int n_in,
                              void* d_out, int out_size) {
    const float* g = (const float*)d_in[0];
    const float* f = (const float*)d_in[1];
    const float* gn = (const float*)d_in[2];
    const float* fn = (const float*)d_in[3];
    const float* nfn = (const float*)d_in[4];
    const float* a = (const float*)d_in[5];
    const float* w2 = (const float*)d_in[6];
    const float* b2 = (const float*)d_in[7];
    const float* w1 = (const float*)d_in[8];
    const float* b1 = (const float*)d_in[9];

    float* out = (float*)d_out;
    float* disf = out + (size_t)NPTS * DP;

    cudaFuncSetAttribute(fused_kernel,
                         cudaFuncAttributeMaxDynamicSharedMemorySize, SMEM_FUSED);
    cudaFuncSetAttribute(out_mma_kernel,
                         cudaFuncAttributeMaxDynamicSharedMemorySize, SMEM_OUT);

    fused_kernel<<<GRID, 512, SMEM_FUSED>>>(nfn, a, g, f, gn, fn, w2, b2, disf);
    out_mma_kernel<<<GRID_OUT, 512, SMEM_OUT>>>(w1, b1, out);
}

// round 14
// speedup vs baseline: 1.0585x; 1.0147x over previous
#include <cuda_runtime.h>
#include <cuda_bf16.h>
#include <mma.h>
#include <math.h>
#include <stdint.h>

using namespace nvcuda;

// ---------------------------------------------------------------------------
#define BB 4
#define NN 4096
#define KK 32
#define DP 128
#define DC 69
#define NPTS (BB*NN)
#define ALPHA 0.2f

#define GRID 152
#define NTILES 8192           // attn: 64 ptk-rows per tile
#define NTILES2 8192          // disf: 64 ptk-rows per tile

__device__ float g_pooled[NPTS * DP];

__device__ __forceinline__ void bf16_split(float v, __nv_bfloat16& h,
                                           __nv_bfloat16& l) {
    h = __float2bfloat16_rn(v);
    l = __float2bfloat16_rn(v - __bfloat162float(h));
}
__device__ __forceinline__ uint32_t pack2(__nv_bfloat16 a, __nv_bfloat16 b) {
    return (uint32_t)__bfloat16_as_ushort(a) |
           ((uint32_t)__bfloat16_as_ushort(b) << 16);
}
__device__ __forceinline__ float2 upk_bf2(uint32_t v) {
    __nv_bfloat162 b = *(__nv_bfloat162*)&v;
    return make_float2(__bfloat162float(b.x), __bfloat162float(b.y));
}
__device__ __forceinline__ uint32_t smem_u32(const void* p) {
    uint32_t a;
    asm("{ .reg .u64 t; cvta.to.shared.u64 t, %1; cvt.u32.u64 %0, t; }"
        : "=r"(a) : "l"(p));
    return a;
}
#define NAMED_BAR(id, cnt) \
    asm volatile("bar.sync %0, %1;" :: "r"(id), "r"(cnt) : "memory")

#define CP_ASYNC16(dst, src) \
    asm volatile("cp.async.cg.shared.global [%0], [%1], 16;" \
        :: "r"((uint32_t)(dst)), "l"(src) : "memory")
#define CP_COMMIT() asm volatile("cp.async.commit_group;" ::: "memory")
#define CP_WAIT0()  asm volatile("cp.async.wait_group 0;" ::: "memory")

__device__ __forceinline__ void ldsm4(uint32_t* r, uint32_t addr) {
    asm volatile("ldmatrix.sync.aligned.m8n8.x4.shared.b16 {%0,%1,%2,%3}, [%4];"
        : "=r"(r[0]), "=r"(r[1]), "=r"(r[2]), "=r"(r[3]) : "r"(addr));
}
__device__ __forceinline__ void ldsm4t(uint32_t* r, uint32_t addr) {
    asm volatile("ldmatrix.sync.aligned.m8n8.x4.trans.shared.b16 {%0,%1,%2,%3}, [%4];"
        : "=r"(r[0]), "=r"(r[1]), "=r"(r[2]), "=r"(r[3]) : "r"(addr));
}
__device__ __forceinline__ void mma16816(float* d, const uint32_t* a,
                                         const uint32_t* b) {
    asm volatile("mma.sync.aligned.m16n8k16.row.col.f32.bf16.bf16.f32 "
        "{%0,%1,%2,%3}, {%4,%5,%6,%7}, {%8,%9}, {%0,%1,%2,%3};"
        : "+f"(d[0]), "+f"(d[1]), "+f"(d[2]), "+f"(d[3])
        : "r"(a[0]), "r"(a[1]), "r"(a[2]), "r"(a[3]), "r"(b[0]), "r"(b[1]));
}

// ---------------------------------------------------------------------------
// Fused kernel smem layout (bytes)
// ---------------------------------------------------------------------------
#define A_LDA 136
#define D_LDW 136
#define D_LDG 88
#define FX_AH   0          // [128][136] bf16 = 34816
#define FX_AL   34816
#define FX_NH   69632      // [64][136] bf16 = 17408
#define FX_NL   87040
#define FX_RAW  104448     // attn staging [64][128] fp32 = 32768
#define FX_W2H  137216     // [80][136] bf16 = 21760
#define FX_W2L  158976
#define FX_DGH  180736     // [64][88] bf16 = 11264
#define FX_DGL  192000
#define SMEM_FUSED 203264

// ============================================================================
// Fused attn+disf: warps 0-7 = attn (cp.async piped, reg-resident epilogue),
// warps 8-15 = disf.
// ============================================================================
__global__ void __launch_bounds__(512, 1)
fused_kernel(const float* __restrict__ nfn, const float* __restrict__ a,
             const float* __restrict__ g, const float* __restrict__ f,
             const float* __restrict__ gn, const float* __restrict__ fn,
             const float* __restrict__ w2, const float* __restrict__ b2,
             float* __restrict__ disf) {
    extern __shared__ char sm[];
    __nv_bfloat16* a_h = (__nv_bfloat16*)(sm + FX_AH);
    __nv_bfloat16* a_l = (__nv_bfloat16*)(sm + FX_AL);
    __nv_bfloat16* n_h = (__nv_bfloat16*)(sm + FX_NH);
    __nv_bfloat16* n_l = (__nv_bfloat16*)(sm + FX_NL);
    float* raw = (float*)(sm + FX_RAW);
    __nv_bfloat16* w2h = (__nv_bfloat16*)(sm + FX_W2H);
    __nv_bfloat16* w2l = (__nv_bfloat16*)(sm + FX_W2L);
    __nv_bfloat16* dgh = (__nv_bfloat16*)(sm + FX_DGH);
    __nv_bfloat16* dgl = (__nv_bfloat16*)(sm + FX_DGL);

    const int tid = threadIdx.x;
    const int bid = blockIdx.x;

    // one-time: split a (attn) and permuted w2+bias (disf)
    for (int idx = tid; idx < 128 * 128; idx += 512) {
        int j = idx >> 7, d = idx & 127;
        __nv_bfloat16 h, l;
        bf16_split(a[idx], h, l);
        a_h[j * A_LDA + d] = h;
        a_l[j * A_LDA + d] = l;
    }
    for (int idx = tid; idx < 80 * 128; idx += 512) {
        int ch = idx >> 7, dd = idx & 127;
        float v = 0.f;
        if (ch < 64) v = w2[(3 + ch) * 128 + dd];
        else if (ch < 67) v = w2[(ch - 64) * 128 + dd];
        else if (ch < 69) v = w2[ch * 128 + dd];
        else if (ch == 69) v = b2[dd];
        __nv_bfloat16 h, l;
        bf16_split(v, h, l);
        w2h[ch * D_LDW + dd] = h;
        w2l[ch * D_LDW + dd] = l;
    }
    __syncthreads();

    if (tid < 256) {
        // ==================== attn pipeline (warps 0-7) ====================
        const int u = tid;
        const int w = u >> 5;
        const int lane = u & 31;
        const int wm = w & 1;
        const int wn = w >> 1;
        const int qrow = lane >> 2;
        const int qc = (lane & 3) << 1;
        const int lrow = lane & 15;
        const int lcol = (lane >> 4) << 3;
        const uint32_t nh_smb = smem_u32(n_h);
        const uint32_t nl_smb = smem_u32(n_l);
        const uint32_t ah_smb = smem_u32(a_h);
        const uint32_t al_smb = smem_u32(a_l);
        const uint32_t raw_smb = smem_u32(raw);

        const int nt = (NTILES - bid + GRID - 1) / GRID;

        // prologue: cp.async tile 0 -> raw
        {
            const char* src = (const char*)(nfn + (size_t)bid * 8192) + u * 16;
            uint32_t dst = raw_smb + u * 16;
#pragma unroll
            for (int q = 0; q < 8; q++) CP_ASYNC16(dst + q * 4096, src + q * 4096);
            CP_COMMIT();
        }

        for (int j = 0; j < nt; j++) {
            const int tile = bid + j * GRID;

            // ---- phase 1: own-thread raw ready; split -> n_h/n_l ----
            // (raw dst == split src per thread: no cross-warp bar needed)
            CP_WAIT0();
#pragma unroll
            for (int q = 0; q < 8; q++) {
                int v = u + 256 * q;
                float4 x = ((const float4*)raw)[v];
                __nv_bfloat16 h0, l0, h1, l1, h2, l2, h3, l3;
                bf16_split(x.x, h0, l0);
                bf16_split(x.y, h1, l1);
                bf16_split(x.z, h2, l2);
                bf16_split(x.w, h3, l3);
                int fidx = v * 4;
                int r = fidx >> 7, c = fidx & 127;
                *(uint2*)(n_h + r * A_LDA + c) =
                    make_uint2(pack2(h0, h1), pack2(h2, h3));
                *(uint2*)(n_l + r * A_LDA + c) =
                    make_uint2(pack2(l0, l1), pack2(l2, l3));
            }
            NAMED_BAR(1, 256);   // (b) split done: n bufs ready

            // next tile's cp.async; overlaps mma below (per-thread region)
            if (j + 1 < nt) {
                const char* src =
                    (const char*)(nfn + (size_t)(bid + (size_t)(j + 1) * GRID) * 8192) +
                    u * 16;
                uint32_t dst = raw_smb + u * 16;
#pragma unroll
                for (int q = 0; q < 8; q++)
                    CP_ASYNC16(dst + q * 4096, src + q * 4096);
                CP_COMMIT();
            }

            // ---- phase 2: mma bf16x3, save h AND l A-frags for epilogue ----
            float acc[2][4][4];
#pragma unroll
            for (int mi = 0; mi < 2; mi++)
#pragma unroll
                for (int ni = 0; ni < 4; ni++)
#pragma unroll
                    for (int r = 0; r < 4; r++) acc[mi][ni][r] = 0.f;

            uint32_t nsav[2][2][4];    // n_h frags at kk = 2wn, 2wn+1
            uint32_t nsav2[2][2][4];   // n_l frags at kk = 2wn, 2wn+1

#pragma unroll
            for (int kk = 0; kk < 8; kk++) {
                uint32_t ah[2][4], al[2][4];
#pragma unroll
                for (int mi = 0; mi < 2; mi++) {
                    const int row = wm * 32 + mi * 16 + lrow;
                    const uint32_t boff =
                        (uint32_t)(row * (A_LDA * 2) + (kk * 16 + lcol) * 2);
                    ldsm4(ah[mi], nh_smb + boff);
                    ldsm4(al[mi], nl_smb + boff);
                }
                if ((kk >> 1) == wn) {
#pragma unroll
                    for (int mi = 0; mi < 2; mi++)
#pragma unroll
                        for (int r = 0; r < 4; r++) {
                            nsav[mi][kk & 1][r] = ah[mi][r];
                            nsav2[mi][kk & 1][r] = al[mi][r];
                        }
                }
#pragma unroll
                for (int grp = 0; grp < 2; grp++) {
                    uint32_t bh[4], bl[4];
                    const uint32_t boff =
                        (uint32_t)((kk * 16 + lrow) * (A_LDA * 2) +
                                   (wn * 32 + grp * 16 + lcol) * 2);
                    ldsm4t(bh, ah_smb + boff);
                    ldsm4t(bl, al_smb + boff);
#pragma unroll
                    for (int mi = 0; mi < 2; mi++)
#pragma unroll
                        for (int jj = 0; jj < 2; jj++) {
                            float* d = acc[mi][grp * 2 + jj];
                            mma16816(d, ah[mi], bh + 2 * jj);
                            mma16816(d, ah[mi], bl + 2 * jj);
                            mma16816(d, al[mi], bh + 2 * jj);
                        }
                }
            }
            NAMED_BAR(1, 256);   // (c) all ldsm reads of n bufs done

            // ---- phase 3: fully register-resident softmax + pooled ----
            // (no smem access: overlaps other warps' next split)
            {
                float es[8], pl[8];
#pragma unroll
                for (int c = 0; c < 8; c++) { es[c] = 0.f; pl[c] = 0.f; }

#pragma unroll
                for (int mi = 0; mi < 2; mi++)
#pragma unroll
                    for (int hr = 0; hr < 2; hr++) {
#pragma unroll
                        for (int ni = 0; ni < 4; ni++) {
                            float2 hp = upk_bf2(
                                nsav[mi][ni >> 1][hr + 2 * (ni & 1)]);
                            float2 lp = upk_bf2(
                                nsav2[mi][ni >> 1][hr + 2 * (ni & 1)]);
                            float n0 = hp.x + lp.x, n1 = hp.y + lp.y;
                            float v0 = acc[mi][ni][hr * 2 + 0];
                            float v1 = acc[mi][ni][hr * 2 + 1];
                            v0 = (v0 > 0.f) ? v0 : ALPHA * v0;
                            v1 = (v1 > 0.f) ? v1 : ALPHA * v1;
                            float e0 = __expf(v0), e1 = __expf(v1);
                            es[ni * 2 + 0] += e0;
                            es[ni * 2 + 1] += e1;
                            pl[ni * 2 + 0] += e0 * n0;
                            pl[ni * 2 + 1] += e1 * n1;
                        }
                    }
#pragma unroll
                for (int c = 0; c < 8; c++) {
#pragma unroll
                    for (int m = 4; m <= 16; m <<= 1) {
                        es[c] += __shfl_xor_sync(0xffffffffu, es[c], m);
                        pl[c] += __shfl_xor_sync(0xffffffffu, pl[c], m);
                    }
                }
                if (lane < 4) {
                    float* dst = g_pooled + (size_t)(tile * 2 + wm) * 128 +
                                 wn * 32 + 2 * lane;
#pragma unroll
                    for (int ni = 0; ni < 4; ni++) {
                        float2 v =
                            make_float2(__fdividef(pl[2 * ni], es[2 * ni]),
                                        __fdividef(pl[2 * ni + 1], es[2 * ni + 1]));
                        *(float2*)(dst + ni * 8) = v;
                    }
                }
            }
        }
    } else {
        // ==================== disf pipeline (warps 8-15) — R11 version =====
        const int u = tid - 256;
        const int w = u >> 5;
        const int wm = w & 1;          // 32-row block
        const int wn = w >> 1;         // 32-col block
        const int r = u >> 2;          // row 0..63
        const int q = u & 3;           // 16-channel chunk
        const int p = r >> 5;

        const int nt = (NTILES2 - bid + GRID - 1) / GRID;
        for (int j = 0; j < nt; j++) {
            const int tile = bid + j * GRID;
            const int grow = tile * 64 + r;

            // ---- build dgf straight from LDG ----
            {
                const float4* fnp =
                    (const float4*)(fn + (size_t)grow * 64 + q * 16);
                const float4* fp =
                    (const float4*)(f + (size_t)(tile * 2 + p) * 64 + q * 16);
                float pf[16];
                float df2 = 0.f;
#pragma unroll
                for (int i = 0; i < 4; i++) {
                    float4 A = fnp[i], F = fp[i];
                    pf[i * 4 + 0] = F.x - A.x;
                    pf[i * 4 + 1] = F.y - A.y;
                    pf[i * 4 + 2] = F.z - A.z;
                    pf[i * 4 + 3] = F.w - A.w;
                    float t0 = F.x - 2.f * A.x, t1 = F.y - 2.f * A.y;
                    float t2 = F.z - 2.f * A.z, t3 = F.w - 2.f * A.w;
                    df2 += t0 * t0 + t1 * t1 + t2 * t2 + t3 * t3;
                }
                uint4* dsth = (uint4*)(dgh + r * D_LDG + q * 16);
                uint4* dstl = (uint4*)(dgl + r * D_LDG + q * 16);
                uint32_t hh[8], ll[8];
#pragma unroll
                for (int i = 0; i < 8; i++) {
                    __nv_bfloat16 h0, l0, h1, l1;
                    bf16_split(pf[2 * i], h0, l0);
                    bf16_split(pf[2 * i + 1], h1, l1);
                    hh[i] = pack2(h0, h1);
                    ll[i] = pack2(l0, l1);
                }
                dsth[0] = make_uint4(hh[0], hh[1], hh[2], hh[3]);
                dsth[1] = make_uint4(hh[4], hh[5], hh[6], hh[7]);
                dstl[0] = make_uint4(ll[0], ll[1], ll[2], ll[3]);
                dstl[1] = make_uint4(ll[4], ll[5], ll[6], ll[7]);

                df2 += __shfl_xor_sync(0xffffffffu, df2, 1);
                df2 += __shfl_xor_sync(0xffffffffu, df2, 2);

                if (q == 0) {
                    float tail[16];
#pragma unroll
                    for (int i = 0; i < 16; i++) tail[i] = 0.f;
                    float dg2 = 0.f;
#pragma unroll
                    for (int c = 0; c < 3; c++) {
                        float gv = g[(size_t)(tile * 2 + p) * 3 + c];
                        float gnv = gn[(size_t)grow * 3 + c];
                        tail[c] = gv - gnv;
                        float t = gv - 2.f * gnv;
                        dg2 += t * t;
                    }
                    tail[3] = sqrtf(dg2);
                    tail[4] = sqrtf(df2);
                    tail[5] = 1.0f;
                    uint32_t th[8], tl[8];
#pragma unroll
                    for (int i = 0; i < 8; i++) {
                        __nv_bfloat16 h0, l0, h1, l1;
                        bf16_split(tail[2 * i], h0, l0);
                        bf16_split(tail[2 * i + 1], h1, l1);
                        th[i] = pack2(h0, h1);
                        tl[i] = pack2(l0, l1);
                    }
                    uint4* dh = (uint4*)(dgh + r * D_LDG + 64);
                    uint4* dl = (uint4*)(dgl + r * D_LDG + 64);
                    dh[0] = make_uint4(th[0], th[1], th[2], th[3]);
                    dh[1] = make_uint4(th[4], th[5], th[6], th[7]);
                    dl[0] = make_uint4(tl[0], tl[1], tl[2], tl[3]);
                    dl[1] = make_uint4(tl[4], tl[5], tl[6], tl[7]);
                }
            }
            NAMED_BAR(2, 256);

            // ---- wmma bf16x3 (K=80), 32x32 warp tiles, store to gmem ----
            {
                wmma::fragment<wmma::accumulator, 16, 16, 16, float> acc[2][2];
#pragma unroll
                for (int mi = 0; mi < 2; mi++)
#pragma unroll
                    for (int ni = 0; ni < 2; ni++)
                        wmma::fill_fragment(acc[mi][ni], 0.0f);
#pragma unroll
                for (int kk = 0; kk < 5; kk++) {
                    wmma::fragment<wmma::matrix_a, 16, 16, 16, __nv_bfloat16,
                                   wmma::row_major> dh[2], dl[2];
#pragma unroll
                    for (int mi = 0; mi < 2; mi++) {
                        const int row = wm * 32 + mi * 16;
                        wmma::load_matrix_sync(dh[mi],
                            dgh + row * D_LDG + kk * 16, D_LDG);
                        wmma::load_matrix_sync(dl[mi],
                            dgl + row * D_LDG + kk * 16, D_LDG);
                    }
#pragma unroll
                    for (int ni = 0; ni < 2; ni++) {
                        wmma::fragment<wmma::matrix_b, 16, 16, 16, __nv_bfloat16,
                                       wmma::row_major> wh, wl;
                        const int col = wn * 32 + ni * 16;
                        wmma::load_matrix_sync(wh,
                            w2h + kk * 16 * D_LDW + col, D_LDW);
                        wmma::load_matrix_sync(wl,
                            w2l + kk * 16 * D_LDW + col, D_LDW);
#pragma unroll
                        for (int mi = 0; mi < 2; mi++) {
                            wmma::mma_sync(acc[mi][ni], dh[mi], wh, acc[mi][ni]);
                            wmma::mma_sync(acc[mi][ni], dh[mi], wl, acc[mi][ni]);
                            wmma::mma_sync(acc[mi][ni], dl[mi], wh, acc[mi][ni]);
                        }
                    }
                }
                float* dst = disf + (size_t)tile * 64 * 128;
#pragma unroll
                for (int mi = 0; mi < 2; mi++)
#pragma unroll
                    for (int ni = 0; ni < 2; ni++)
                        wmma::store_matrix_sync(
                            dst + (wm * 32 + mi * 16) * 128 + wn * 32 + ni * 16,
                            acc[mi][ni], 128, wmma::mem_row_major);
            }
            NAMED_BAR(2, 256);
        }
    }
}

// ============================================================================
// out = pooled @ w1 + b1 (R13 version, unchanged).
// ============================================================================
#define O_LDW 136
#define GRID_OUT 128
#define OT_WH 0
#define OT_WL 34816
#define OT_B1 69632
#define OT_HB 70144
#define OT_HSZ 34816
#define SMEM_OUT 139776

__global__ void __launch_bounds__(512, 1)
out_mma_kernel(const float* __restrict__ w1, const float* __restrict__ b1,
               float* __restrict__ out) {
    extern __shared__ char sm[];
    __nv_bfloat16* w1h = (__nv_bfloat16*)(sm + OT_WH);
    __nv_bfloat16* w1l = (__nv_bfloat16*)(sm + OT_WL);
    float* b1s = (float*)(sm + OT_B1);

    const int tid = threadIdx.x;
    const int half = tid >> 8;
    const int u = tid & 255;

    for (int idx = tid; idx < 128 * 128; idx += 512) {
        int j = idx >> 7, d = idx & 127;
        __nv_bfloat16 h, l;
        bf16_split(w1[idx], h, l);
        w1h[j * O_LDW + d] = h;
        w1l[j * O_LDW + d] = l;
    }
    if (tid < 128) b1s[tid] = b1[tid];
    __syncthreads();

    char* hb = sm + OT_HB + half * OT_HSZ;
    __nv_bfloat16* p_h = (__nv_bfloat16*)hb;
    __nv_bfloat16* p_l = (__nv_bfloat16*)(hb + 17408);

    const int tile = blockIdx.x * 2 + half;

    {
        const float4* gsrc = (const float4*)(g_pooled + (size_t)tile * 8192);
#pragma unroll
        for (int q = 0; q < 8; q++) {
            int v = u + 256 * q;
            float4 x = gsrc[v];
            __nv_bfloat16 h0, l0, h1, l1, h2, l2, h3, l3;
            bf16_split(x.x, h0, l0);
            bf16_split(x.y, h1, l1);
            bf16_split(x.z, h2, l2);
            bf16_split(x.w, h3, l3);
            int fidx = v * 4;
            int r = fidx >> 7, c = fidx & 127;
            *(uint2*)(p_h + r * O_LDW + c) = make_uint2(pack2(h0, h1), pack2(h2, h3));
            *(uint2*)(p_l + r * O_LDW + c) = make_uint2(pack2(l0, l1), pack2(l2, l3));
        }
    }
    NAMED_BAR(1 + half, 256);

    const int w = u >> 5;
    const int lane = u & 31;
    const int wm = w & 3;
    const int wn = w >> 2;
    const int qrow = lane >> 2;
    const int qc = (lane & 3) << 1;
    const int lrow = lane & 15;
    const int lcol = (lane >> 4) << 3;
    const uint32_t ph_smb = smem_u32(p_h);
    const uint32_t pl_smb = smem_u32(p_l);
    const uint32_t wh_smb = smem_u32(w1h);
    const uint32_t wl_smb = smem_u32(w1l);

    float2 b1v[8];
#pragma unroll
    for (int grp = 0; grp < 4; grp++)
#pragma unroll
        for (int jj = 0; jj < 2; jj++) {
            int col = wn * 64 + grp * 16 + jj * 8 + qc;
            b1v[grp * 2 + jj] = *(const float2*)(b1s + col);
        }

    float acc[8][4];
#pragma unroll
    for (int c = 0; c < 8; c++)
#pragma unroll
        for (int r = 0; r < 4; r++) acc[c][r] = 0.f;

#pragma unroll
    for (int kk = 0; kk < 8; kk++) {
        uint32_t ph[4], pl[4];
        {
            const int row = wm * 16 + lrow;
            const uint32_t boff =
                (uint32_t)(row * (O_LDW * 2) + (kk * 16 + lcol) * 2);
            ldsm4(ph, ph_smb + boff);
            ldsm4(pl, pl_smb + boff);
        }
#pragma unroll
        for (int grp = 0; grp < 4; grp++) {
            uint32_t bh[4], bl[4];
            const uint32_t boff =
                (uint32_t)((kk * 16 + lrow) * (O_LDW * 2) +
                           (wn * 64 + grp * 16 + lcol) * 2);
            ldsm4t(bh, wh_smb + boff);
            ldsm4t(bl, wl_smb + boff);
#pragma unroll
            for (int jj = 0; jj < 2; jj++) {
                float* d = acc[grp * 2 + jj];
                mma16816(d, ph, bh + 2 * jj);
                mma16816(d, ph, bl + 2 * jj);
                mma16816(d, pl, bh + 2 * jj);
            }
        }
    }

    {
        float* base = out + (size_t)tile * 8192;
#pragma unroll
        for (int grp = 0; grp < 4; grp++)
#pragma unroll
            for (int jj = 0; jj < 2; jj++) {
                const int c8 = grp * 2 + jj;
                const int col = wn * 64 + grp * 16 + jj * 8 + qc;
#pragma unroll
                for (int hr = 0; hr < 2; hr++) {
                    const int row = wm * 16 + qrow + 8 * hr;
                    float2 v = make_float2(acc[c8][hr * 2 + 0] + b1v[c8].x,
                                           acc[c8][hr * 2 + 1] + b1v[c8].y);
                    *(float2*)(base + row * 128 + col) = v;
                }
            }
    }
}

// ============================================================================
// launch
// ============================================================================
extern "C" void kernel_launch(void* const* d_in, const int* in_sizes, int n_in,
                              void* d_out, int out_size) {
    const float* g = (const float*)d_in[0];
    const float* f = (const float*)d_in[1];
    const float* gn = (const float*)d_in[2];
    const float* fn = (const float*)d_in[3];
    const float* nfn = (const float*)d_in[4];
    const float* a = (const float*)d_in[5];
    const float* w2 = (const float*)d_in[6];
    const float* b2 = (const float*)d_in[7];
    const float* w1 = (const float*)d_in[8];
    const float* b1 = (const float*)d_in[9];

    float* out = (float*)d_out;
    float* disf = out + (size_t)NPTS * DP;

    cudaFuncSetAttribute(fused_kernel,
                         cudaFuncAttributeMaxDynamicSharedMemorySize, SMEM_FUSED);
    cudaFuncSetAttribute(out_mma_kernel,
                         cudaFuncAttributeMaxDynamicSharedMemorySize, SMEM_OUT);

    fused_kernel<<<GRID, 512, SMEM_FUSED>>>(nfn, a, g, f, gn, fn, w2, b2, disf);
    out_mma_kernel<<<GRID_OUT, 512, SMEM_OUT>>>(w1, b1, out);
}